// round 12
// baseline (speedup 1.0000x reference)
#include <cuda_runtime.h>
#include <cuda_fp16.h>
#include <math.h>

#define BATCH 256
#define SEQT  512
#define VOCAB 50000
#define EMB   300
#define HID   256
#define GATES 1024   // 4*HID
#define NBLK  128
// sWb (32768 u32) + sh2 (16*132 u32) + mbarrier (8B)
#define SMEM_RNN ((32768 + 2112)*4 + 16)

// Scratch (static device memory — allocation-free)
__device__ float    d_proj[VOCAB][2*GATES];    // [v][dir*1024 + hc*4 + g], bias folded in
__device__ unsigned d_hbuf[2][2][BATCH][132];  // fp16 pairs, k-permuted
__device__ float    d_hfinal[2][BATCH][HID];   // fp32 final hidden state
__device__ int      d_len[BATCH];

__device__ __forceinline__ float tanha(float x){
    float y; asm("tanh.approx.f32 %0, %1;" : "=f"(y) : "f"(x)); return y;
}
__device__ __forceinline__ float sigt(float x){
    return fmaf(tanha(0.5f*x), 0.5f, 0.5f);
}
// pair-permutation inside a 16-k block: pair j -> slot (j&3)*2 + (j>>2)
__device__ __forceinline__ int hslot(int k){   // k even; returns u32 index
    int blk = k >> 4, j = (k & 15) >> 1;
    return blk*8 + (j & 3)*2 + (j >> 2);
}
__device__ __forceinline__ unsigned packh2(float a, float b){
    __half2 hv = __halves2half2(__float2half_rn(a), __float2half_rn(b));
    return *(unsigned*)&hv;
}
__device__ __forceinline__ void cp16(unsigned dst_smem, const void* src, int szbytes){
    asm volatile("cp.async.cg.shared.global [%0], [%1], 16, %2;"
                 :: "r"(dst_smem), "l"(src), "r"(szbytes));
}
__device__ __forceinline__ unsigned mapa_u32(unsigned addr, unsigned rank){
    unsigned r;
    asm("mapa.shared::cluster.u32 %0, %1, %2;" : "=r"(r) : "r"(addr), "r"(rank));
    return r;
}
// cluster-scope release arrive on a (possibly remote) cluster-CTA mbarrier
__device__ __forceinline__ void mbar_arrive_cluster(unsigned remote_addr){
    asm volatile("mbarrier.arrive.release.cluster.shared::cluster.b64 _, [%0];"
                 :: "r"(remote_addr) : "memory");
}
// cluster-scope acquire wait on the local mbarrier (HW-sleep try_wait loop)
__device__ __forceinline__ void mbar_wait_cluster(unsigned addr, unsigned parity){
    asm volatile(
        "{\n\t"
        ".reg .pred P;\n\t"
        "WL_%=:\n\t"
        "mbarrier.try_wait.parity.acquire.cluster.shared::cta.b64 P, [%0], %1, 0x989680;\n\t"
        "@P bra.uni WD_%=;\n\t"
        "bra.uni WL_%=;\n\t"
        "WD_%=:\n\t"
        "}"
        :: "r"(addr), "r"(parity) : "memory");
}

// ---------------------------------------------------------------------------
// Kernel 1: lengths + zero initial (permuted-fp16) h states
// ---------------------------------------------------------------------------
__global__ void k_init(const int* __restrict__ ids){
    int b = blockIdx.x;
    __shared__ int cnt;
    if (threadIdx.x == 0) cnt = 0;
    __syncthreads();
    int c = 0;
    for (int t = threadIdx.x; t < SEQT; t += blockDim.x)
        c += (ids[b*SEQT + t] != 0);
    #pragma unroll
    for (int o = 16; o; o >>= 1) c += __shfl_down_sync(0xffffffffu, c, o);
    if ((threadIdx.x & 31) == 0) atomicAdd(&cnt, c);
    __syncthreads();
    if (threadIdx.x == 0) d_len[b] = cnt;
    for (int i = threadIdx.x; i < 132; i += blockDim.x){
        d_hbuf[0][0][b][i] = 0u;
        d_hbuf[0][1][b][i] = 0u;
        d_hbuf[1][0][b][i] = 0u;
        d_hbuf[1][1][b][i] = 0u;
    }
}

// ---------------------------------------------------------------------------
// Kernel 2: vocab projection GEMM via tf32 mma with cp.async double-buffered
// smem pipeline (unchanged from R11, 2445us-proven).
// ---------------------------------------------------------------------------
#define NIT 19   // ceil(304/16)
__global__ void __launch_bounds__(256, 2)
k_vgemm(const float* __restrict__ emb,
        const float* __restrict__ Wfw, const float* __restrict__ bfw,
        const float* __restrict__ Wbw, const float* __restrict__ bbw){
    __shared__ float As[2][128][20];     // [buf][m][k] rows 80B (16B-aligned)
    __shared__ float Bs[2][16][132];     // [buf][k][n]
    int nx  = blockIdx.x;
    int dir = nx >> 3;
    int n0  = (nx & 7) * 128;
    int m0  = blockIdx.y * 128;
    const float* __restrict__ Wg = dir ? Wbw : Wfw;
    const float* __restrict__ bg = dir ? bbw : bfw;

    int t    = threadIdx.x;
    int lane = t & 31;
    int w    = t >> 5;
    int wm   = w & 1;
    int wn   = w >> 1;

    unsigned sA = (unsigned)__cvta_generic_to_shared(&As[0][0][0]);
    unsigned sB = (unsigned)__cvta_generic_to_shared(&Bs[0][0][0]);

    auto load_stage = [&](int it, int bf){
        int k0 = it*16;
        #pragma unroll
        for (int i = 0; i < 2; i++){
            int idx = t + i*256;
            int m   = idx >> 2;
            int kk4 = (idx & 3)*4;
            int gm  = m0 + m;
            int ok  = (gm < VOCAB && (k0 + kk4) < EMB) ? 16 : 0;
            const float* src = &emb[(size_t)gm*EMB + k0 + kk4];
            if (gm >= VOCAB) src = emb;
            cp16(sA + (unsigned)(bf*128*20 + m*20 + kk4)*4u, src, ok);
        }
        #pragma unroll
        for (int i = 0; i < 2; i++){
            int idx = t + i*256;
            int kk  = idx >> 5;
            int nn4 = (idx & 31)*4;
            int ok  = (k0 + kk < EMB) ? 16 : 0;
            const float* src = &Wg[(size_t)(k0 + kk)*GATES + n0 + nn4];
            if (k0 + kk >= EMB) src = Wg;
            cp16(sB + (unsigned)(bf*16*132 + kk*132 + nn4)*4u, src, ok);
        }
        asm volatile("cp.async.commit_group;" ::: "memory");
    };

    float acc[4][4][4] = {};

    load_stage(0, 0);
    for (int it = 0; it < NIT; it++){
        int bf = it & 1;
        if (it + 1 < NIT){
            load_stage(it + 1, bf ^ 1);
            asm volatile("cp.async.wait_group 1;" ::: "memory");
        } else {
            asm volatile("cp.async.wait_group 0;" ::: "memory");
        }
        __syncthreads();

        #pragma unroll
        for (int k8 = 0; k8 < 2; k8++){
            int k = k8*8 + (lane & 3);
            unsigned a[4][4], b[4][2];
            #pragma unroll
            for (int mi = 0; mi < 4; mi++){
                int row = wm*64 + mi*16 + (lane >> 2);
                a[mi][0] = __float_as_uint(As[bf][row    ][k]);
                a[mi][1] = __float_as_uint(As[bf][row + 8][k]);
                a[mi][2] = __float_as_uint(As[bf][row    ][k + 4]);
                a[mi][3] = __float_as_uint(As[bf][row + 8][k + 4]);
            }
            #pragma unroll
            for (int ni = 0; ni < 4; ni++){
                int n = wn*32 + ni*8 + (lane >> 2);
                b[ni][0] = __float_as_uint(Bs[bf][k    ][n]);
                b[ni][1] = __float_as_uint(Bs[bf][k + 4][n]);
            }
            #pragma unroll
            for (int mi = 0; mi < 4; mi++)
                #pragma unroll
                for (int ni = 0; ni < 4; ni++)
                    asm volatile(
                        "mma.sync.aligned.m16n8k8.row.col.f32.tf32.tf32.f32 "
                        "{%0,%1,%2,%3},{%4,%5,%6,%7},{%8,%9},{%0,%1,%2,%3};"
                        : "+f"(acc[mi][ni][0]), "+f"(acc[mi][ni][1]),
                          "+f"(acc[mi][ni][2]), "+f"(acc[mi][ni][3])
                        : "r"(a[mi][0]), "r"(a[mi][1]), "r"(a[mi][2]), "r"(a[mi][3]),
                          "r"(b[ni][0]), "r"(b[ni][1]));
        }
        __syncthreads();
    }

    #pragma unroll
    for (int mi = 0; mi < 4; mi++){
        int rbase = m0 + wm*64 + mi*16 + (lane >> 2);
        #pragma unroll
        for (int ni = 0; ni < 4; ni++){
            int cbase = n0 + wn*32 + ni*8 + (lane & 3)*2;
            #pragma unroll
            for (int c = 0; c < 4; c++){
                int gm  = rbase + (c >> 1)*8;
                int col = cbase + (c & 1);
                if (gm >= VOCAB) continue;
                int g  = col >> 8;
                int hc = col & 255;
                d_proj[gm][dir*GATES + hc*4 + g] = acc[mi][ni][c] + bg[col];
            }
        }
    }
}

// ---------------------------------------------------------------------------
// Kernel 3: persistent bidirectional LSTM — R9/R11 data path (frozen), with
// the per-step barrier.cluster pair replaced by an mbarrier rendezvous:
// each CTA hosts one mbarrier (count=4); threads 0..3 arrive on rank-tid's
// barrier (release.cluster) after a __syncthreads; step start waits with
// try_wait.parity.acquire.cluster (~60-90cyc wakeup vs ~490 UCGABAR_WAIT,
// and no per-step CCTL.IVALL).
// ---------------------------------------------------------------------------
__global__ void __launch_bounds__(256, 1) __cluster_dims__(4, 1, 1)
k_rnn(const float* __restrict__ Wfw, const float* __restrict__ Wbw,
      const int* __restrict__ ids){
    extern __shared__ unsigned smem_u[];
    unsigned* sWb = smem_u;            // 2 regions x [wg 0..7][kb][lane] uint4 fp16 B frags
    unsigned* sh2 = smem_u + 32768;    // [16][132] fp16 pairs, k-permuted
    unsigned  mbar_addr = (unsigned)__cvta_generic_to_shared(&smem_u[32768 + 2112]);

    int tid = threadIdx.x;
    int bid = blockIdx.x;
    int dir = bid >> 6;
    int tl  = bid & 63;
    int b0  = (tl >> 2) * 16;          // batch tile (16 rows)
    int h0  = (tl & 3) * 64;           // hid tile (64 cols) == cluster rank * 64
    const float* __restrict__ Wg = dir ? Wbw : Wfw;

    int lane = tid & 31;
    int wg   = tid >> 5;    // warp id = hid group of 8 (0..7)
    int gid  = lane >> 2;
    int qq   = lane & 3;

    // ---- Fill Wh fp16 B-fragments once, uint4-packed per (wg,kb,lane) ----
    for (int f = tid; f < 32768; f += 256){
        int s   = f & 1;
        int gg  = (f >> 1) & 1;
        int ln  = (f >> 2) & 31;
        int kb  = (f >> 7) & 15;
        int wgf = (f >> 11) & 7;
        int r   = (f >> 14) & 1;
        int g   = r*2 + gg;
        int k   = kb*16 + (ln & 3)*2 + s*8;
        int col = g*HID + h0 + wgf*8 + (ln >> 2);
        sWb[r*16384 + ((wgf*16 + kb)*32 + ln)*4 + gg*2 + s] =
            packh2(Wg[(EMB + k)*GATES + col], Wg[(EMB + k + 1)*GATES + col]);
    }

    // init this CTA's mbarrier (4 arrivals per phase: one from each cluster CTA)
    if (tid == 0)
        asm volatile("mbarrier.init.shared.b64 [%0], 4;" :: "r"(mbar_addr) : "memory");
    __syncthreads();
    // all cluster CTAs' mbarrier inits must be visible before any remote arrive
    asm volatile("barrier.cluster.arrive.aligned;" ::: "memory");
    asm volatile("barrier.cluster.wait.aligned;"   ::: "memory");

    // precompute this thread's remote-arrive address (threads 0..3 only)
    unsigned arr_addr = 0;
    if (tid < 4) arr_addr = mapa_u32(mbar_addr, (unsigned)tid);

    int rb0 = gid;              // block-local batch rows this thread owns
    int rb1 = gid + 8;
    int hc0 = wg*8 + qq*2;      // block-local hidden cols (one fp16 pair), 0..63
    int len0 = d_len[b0 + rb0];
    int len1 = d_len[b0 + rb1];
    float c_reg[4] = {0.f,0.f,0.f,0.f};
    float h_reg[4] = {0.f,0.f,0.f,0.f};
    int   wslot = hslot(h0 + hc0);

    // prefetch xz for t=0
    const int row0 = (b0 + rb0)*SEQT;
    const int row1 = (b0 + rb1)*SEQT;
    float4 xzn0, xzn1, xzn2, xzn3;
    {
        int teff = dir ? (SEQT - 1) : 0;
        int id0 = __ldg(&ids[row0 + teff]);
        int id1 = __ldg(&ids[row1 + teff]);
        const float* p0 = &d_proj[id0][dir*GATES];
        const float* p1 = &d_proj[id1][dir*GATES];
        xzn0 = *(const float4*)&p0[(h0 + hc0    )*4];
        xzn1 = *(const float4*)&p0[(h0 + hc0 + 1)*4];
        xzn2 = *(const float4*)&p1[(h0 + hc0    )*4];
        xzn3 = *(const float4*)&p1[(h0 + hc0 + 1)*4];
    }

    // phase-0 arrivals (initial h state in d_hbuf[..][0] written by k_init)
    if (tid < 4) mbar_arrive_cluster(arr_addr);

    for (int t = 0; t < SEQT; t++){
        int cur = t & 1, nxt = cur ^ 1;
        int teff = dir ? (SEQT - 1 - t) : t;

        // wait for phase t (parity t&1); acquire.cluster orders peers' h STGs
        mbar_wait_cluster(mbar_addr, (unsigned)(t & 1));

        // stage current h: flat contiguous copy (16 rows x 132 u32 = 528 uint4)
        {
            const uint4* src = (const uint4*)&d_hbuf[dir][cur][b0][0];
            uint4* dst = (uint4*)sh2;
            dst[tid]       = __ldcg(&src[tid]);
            dst[tid + 256] = __ldcg(&src[tid + 256]);
            if (tid < 16) dst[tid + 512] = __ldcg(&src[tid + 512]);
        }
        __syncthreads();

        // accumulators initialized with prefetched xz (bias + input projection)
        float acc[4][4];
        acc[0][0]=xzn0.x; acc[1][0]=xzn0.y; acc[2][0]=xzn0.z; acc[3][0]=xzn0.w;
        acc[0][1]=xzn1.x; acc[1][1]=xzn1.y; acc[2][1]=xzn1.z; acc[3][1]=xzn1.w;
        acc[0][2]=xzn2.x; acc[1][2]=xzn2.y; acc[2][2]=xzn2.z; acc[3][2]=xzn2.w;
        acc[0][3]=xzn3.x; acc[1][3]=xzn3.y; acc[2][3]=xzn3.z; acc[3][3]=xzn3.w;

        #pragma unroll
        for (int kb = 0; kb < 16; kb++){
            uint2 aA = *(const uint2*)&sh2[rb0*132 + kb*8 + qq*2];
            uint2 aB = *(const uint2*)&sh2[rb1*132 + kb*8 + qq*2];
            uint4 B01 = *(const uint4*)&sWb[        ((wg*16 + kb)*32 + lane)*4];
            uint4 B23 = *(const uint4*)&sWb[16384 + ((wg*16 + kb)*32 + lane)*4];
            asm volatile(
                "mma.sync.aligned.m16n8k16.row.col.f32.f16.f16.f32 "
                "{%0,%1,%2,%3},{%4,%5,%6,%7},{%8,%9},{%0,%1,%2,%3};"
                : "+f"(acc[0][0]), "+f"(acc[0][1]), "+f"(acc[0][2]), "+f"(acc[0][3])
                : "r"(aA.x), "r"(aB.x), "r"(aA.y), "r"(aB.y), "r"(B01.x), "r"(B01.y));
            asm volatile(
                "mma.sync.aligned.m16n8k16.row.col.f32.f16.f16.f32 "
                "{%0,%1,%2,%3},{%4,%5,%6,%7},{%8,%9},{%0,%1,%2,%3};"
                : "+f"(acc[1][0]), "+f"(acc[1][1]), "+f"(acc[1][2]), "+f"(acc[1][3])
                : "r"(aA.x), "r"(aB.x), "r"(aA.y), "r"(aB.y), "r"(B01.z), "r"(B01.w));
            asm volatile(
                "mma.sync.aligned.m16n8k16.row.col.f32.f16.f16.f32 "
                "{%0,%1,%2,%3},{%4,%5,%6,%7},{%8,%9},{%0,%1,%2,%3};"
                : "+f"(acc[2][0]), "+f"(acc[2][1]), "+f"(acc[2][2]), "+f"(acc[2][3])
                : "r"(aA.x), "r"(aB.x), "r"(aA.y), "r"(aB.y), "r"(B23.x), "r"(B23.y));
            asm volatile(
                "mma.sync.aligned.m16n8k16.row.col.f32.f16.f16.f32 "
                "{%0,%1,%2,%3},{%4,%5,%6,%7},{%8,%9},{%0,%1,%2,%3};"
                : "+f"(acc[3][0]), "+f"(acc[3][1]), "+f"(acc[3][2]), "+f"(acc[3][3])
                : "r"(aA.x), "r"(aB.x), "r"(aA.y), "r"(aB.y), "r"(B23.z), "r"(B23.w));
        }

        // elementwise LSTM cell (tanh.approx activations)
        {
            bool v0 = (teff < len0);
            bool v1 = (teff < len1);
            #pragma unroll
            for (int ci = 0; ci < 4; ci++){
                float zi = acc[0][ci], zj = acc[1][ci];
                float zf = acc[2][ci], zo = acc[3][ci];
                float nc = c_reg[ci]*sigt(zf + 1.0f) + sigt(zi)*tanha(zj);
                float nh = tanha(nc)*sigt(zo);
                bool v = (ci < 2) ? v0 : v1;
                if (v){ c_reg[ci] = nc; h_reg[ci] = nh; }
            }
        }

        // write new h pairs to the global exchange buffer (L2)
        d_hbuf[dir][nxt][b0 + rb0][wslot] = packh2(h_reg[0], h_reg[1]);
        d_hbuf[dir][nxt][b0 + rb1][wslot] = packh2(h_reg[2], h_reg[3]);

        // prefetch next step's xz (flies under rendezvous + next stage + MMA)
        if (t + 1 < SEQT){
            int tn = dir ? (SEQT - 2 - t) : (t + 1);
            int id0 = __ldg(&ids[row0 + tn]);
            int id1 = __ldg(&ids[row1 + tn]);
            const float* p0 = &d_proj[id0][dir*GATES];
            const float* p1 = &d_proj[id1][dir*GATES];
            xzn0 = *(const float4*)&p0[(h0 + hc0    )*4];
            xzn1 = *(const float4*)&p0[(h0 + hc0 + 1)*4];
            xzn2 = *(const float4*)&p1[(h0 + hc0    )*4];
            xzn3 = *(const float4*)&p1[(h0 + hc0 + 1)*4];
        }

        // order all threads' h STGs before the release-arrives, then arrive
        __syncthreads();
        if (tid < 4) mbar_arrive_cluster(arr_addr);
    }
    // final wait (phase SEQT, parity 0): all remote arrivals landed -> safe exit
    mbar_wait_cluster(mbar_addr, 0u);

    // write fp32 final hidden state
    d_hfinal[dir][b0 + rb0][h0 + hc0    ] = h_reg[0];
    d_hfinal[dir][b0 + rb0][h0 + hc0 + 1] = h_reg[1];
    d_hfinal[dir][b0 + rb1][h0 + hc0    ] = h_reg[2];
    d_hfinal[dir][b0 + rb1][h0 + hc0 + 1] = h_reg[3];
}

// ---------------------------------------------------------------------------
// Kernel 4: final projection scores = [h_fw | h_bw] @ W_out + b_out
// ---------------------------------------------------------------------------
__global__ void k_out(const float* __restrict__ Wout, const float* __restrict__ bout,
                      float* __restrict__ out){
    int b = blockIdx.x;
    int tid = threadIdx.x;
    float s0 = 0.0f, s1 = 0.0f;
    for (int k = tid; k < 512; k += 256){
        float v = (k < 256) ? d_hfinal[0][b][k] : d_hfinal[1][b][k - 256];
        s0 += v*Wout[2*k];
        s1 += v*Wout[2*k + 1];
    }
    #pragma unroll
    for (int o = 16; o; o >>= 1){
        s0 += __shfl_down_sync(0xffffffffu, s0, o);
        s1 += __shfl_down_sync(0xffffffffu, s1, o);
    }
    __shared__ float r0[8], r1[8];
    int w = tid >> 5;
    if ((tid & 31) == 0){ r0[w] = s0; r1[w] = s1; }
    __syncthreads();
    if (tid == 0){
        float t0 = bout[0], t1 = bout[1];
        #pragma unroll
        for (int i = 0; i < 8; i++){ t0 += r0[i]; t1 += r1[i]; }
        out[2*b]     = t0;
        out[2*b + 1] = t1;
    }
}

// ---------------------------------------------------------------------------
extern "C" void kernel_launch(void* const* d_in, const int* in_sizes, int n_in,
                              void* d_out, int out_size){
    const int*   ids  = (const int*)  d_in[0];
    const float* emb  = (const float*)d_in[1];
    const float* Wfw  = (const float*)d_in[2];
    const float* bfw  = (const float*)d_in[3];
    const float* Wbw  = (const float*)d_in[4];
    const float* bbw  = (const float*)d_in[5];
    const float* Wout = (const float*)d_in[6];
    const float* bout = (const float*)d_in[7];
    float* out = (float*)d_out;

    cudaFuncSetAttribute(k_rnn, cudaFuncAttributeMaxDynamicSharedMemorySize, SMEM_RNN);

    k_init<<<BATCH, 128>>>(ids);
    dim3 g2(16, (VOCAB + 127)/128);
    k_vgemm<<<g2, 256>>>(emb, Wfw, bfw, Wbw, bbw);
    k_rnn<<<NBLK, 256, SMEM_RNN>>>(Wfw, Wbw, ids);
    k_out<<<BATCH, 256>>>(Wout, bout, out);
}

// round 13
// speedup vs baseline: 1.1388x; 1.1388x over previous
#include <cuda_runtime.h>
#include <cuda_fp16.h>
#include <math.h>

#define BATCH 256
#define SEQT  512
#define VOCAB 50000
#define EMB   300
#define HID   256
#define GATES 1024   // 4*HID
#define NBLK  128
// sWb (32768 u32) + sh2 (16*132 u32)
#define SMEM_RNN (32768*4 + 2112*4)

// Scratch (static device memory — allocation-free)
__device__ float    d_proj[VOCAB][2*GATES];    // [v][dir*1024 + hc*4 + g], bias folded in
__device__ unsigned d_hbuf[2][2][BATCH][132];  // fp16 pairs, k-permuted
__device__ float    d_hfinal[2][BATCH][HID];   // fp32 final hidden state
__device__ int      d_len[BATCH];
__device__ __half   d_embh[(size_t)VOCAB*304];     // fp16 emb, k padded to 304
__device__ __half   d_wxh[(size_t)2*GATES*304];    // fp16 Wx, n-major: [dir*1024+n][k]

__device__ __forceinline__ float tanha(float x){
    float y; asm("tanh.approx.f32 %0, %1;" : "=f"(y) : "f"(x)); return y;
}
__device__ __forceinline__ float sigt(float x){
    return fmaf(tanha(0.5f*x), 0.5f, 0.5f);
}
// pair-permutation inside a 16-k block: pair j -> slot (j&3)*2 + (j>>2)
__device__ __forceinline__ int hslot(int k){   // k even; returns u32 index
    int blk = k >> 4, j = (k & 15) >> 1;
    return blk*8 + (j & 3)*2 + (j >> 2);
}
__device__ __forceinline__ unsigned packh2(float a, float b){
    __half2 hv = __halves2half2(__float2half_rn(a), __float2half_rn(b));
    return *(unsigned*)&hv;
}
__device__ __forceinline__ void cp16(unsigned dst_smem, const void* src, int szbytes){
    asm volatile("cp.async.cg.shared.global [%0], [%1], 16, %2;"
                 :: "r"(dst_smem), "l"(src), "r"(szbytes));
}

// ---------------------------------------------------------------------------
// Kernel 1: lengths + zero initial (permuted-fp16) h states
// ---------------------------------------------------------------------------
__global__ void k_init(const int* __restrict__ ids){
    int b = blockIdx.x;
    __shared__ int cnt;
    if (threadIdx.x == 0) cnt = 0;
    __syncthreads();
    int c = 0;
    for (int t = threadIdx.x; t < SEQT; t += blockDim.x)
        c += (ids[b*SEQT + t] != 0);
    #pragma unroll
    for (int o = 16; o; o >>= 1) c += __shfl_down_sync(0xffffffffu, c, o);
    if ((threadIdx.x & 31) == 0) atomicAdd(&cnt, c);
    __syncthreads();
    if (threadIdx.x == 0) d_len[b] = cnt;
    for (int i = threadIdx.x; i < 132; i += blockDim.x){
        d_hbuf[0][0][b][i] = 0u;
        d_hbuf[0][1][b][i] = 0u;
        d_hbuf[1][0][b][i] = 0u;
        d_hbuf[1][1][b][i] = 0u;
    }
}

// ---------------------------------------------------------------------------
// Kernel 1b: one-shot fp16 conversions
// ---------------------------------------------------------------------------
__global__ void k_cvt_emb(const float* __restrict__ emb){
    int idx = blockIdx.x*blockDim.x + threadIdx.x;   // over VOCAB*76
    if (idx >= VOCAB*76) return;
    int v  = idx / 76;
    int k4 = (idx % 76)*4;
    __half2 h0, h1;
    if (k4 < EMB){
        float4 f = *(const float4*)&emb[(size_t)v*EMB + k4];
        h0 = __floats2half2_rn(f.x, f.y);
        h1 = __floats2half2_rn(f.z, f.w);
    } else {
        h0 = __floats2half2_rn(0.f, 0.f);
        h1 = h0;
    }
    *(__half2*)&d_embh[(size_t)v*304 + k4    ] = h0;
    *(__half2*)&d_embh[(size_t)v*304 + k4 + 2] = h1;
}

__global__ void k_cvt_w(const float* __restrict__ Wfw, const float* __restrict__ Wbw){
    int idx = blockIdx.x*blockDim.x + threadIdx.x;   // over 2*1024*76
    if (idx >= 2*GATES*76) return;
    int dir = idx / (GATES*76);
    int r   = idx % (GATES*76);
    int n   = r / 76;
    int k4  = (r % 76)*4;
    const float* W = dir ? Wbw : Wfw;
    float f0=0.f, f1=0.f, f2=0.f, f3=0.f;
    if (k4 < EMB){
        f0 = W[(k4    )*GATES + n];
        f1 = W[(k4 + 1)*GATES + n];
        f2 = W[(k4 + 2)*GATES + n];
        f3 = W[(k4 + 3)*GATES + n];
    }
    size_t o = ((size_t)dir*GATES + n)*304 + k4;
    *(__half2*)&d_wxh[o    ] = __floats2half2_rn(f0, f1);
    *(__half2*)&d_wxh[o + 2] = __floats2half2_rn(f2, f3);
}

// ---------------------------------------------------------------------------
// Kernel 2: vocab projection GEMM via fp16 m16n8k16 mma with cp.async
// double-buffered pipeline. A: [m][24] halves (48B rows), B: [n][24] halves
// (n-major, pre-transposed in d_wxh). fp32 accumulate; bias in fp32 epilogue.
// ---------------------------------------------------------------------------
#define NIT 19   // 304/16
__global__ void __launch_bounds__(256, 2)
k_vgemm(const float* __restrict__ bfw, const float* __restrict__ bbw){
    __shared__ __half As[2][128][24];    // 48B rows -> conflict-free frags
    __shared__ __half Bs[2][128][24];
    int nx  = blockIdx.x;
    int dir = nx >> 3;
    int n0  = (nx & 7) * 128;
    int m0  = blockIdx.y * 128;
    const float*  __restrict__ bg = dir ? bbw : bfw;
    const __half* __restrict__ Wg = d_wxh + (size_t)dir*GATES*304;

    int t    = threadIdx.x;
    int lane = t & 31;
    int w    = t >> 5;
    int wm   = w & 1;
    int wn   = w >> 1;
    int q    = lane & 3;
    int g    = lane >> 2;

    unsigned sA = (unsigned)__cvta_generic_to_shared(&As[0][0][0]);
    unsigned sB = (unsigned)__cvta_generic_to_shared(&Bs[0][0][0]);

    // async-load one 16-k stage into buffer bf (1 A-chunk + 1 B-chunk/thread)
    auto load_stage = [&](int it, int bf){
        int k0 = it*16;
        int m  = t >> 1;           // 0..127
        int c  = t & 1;            // chunk (8 halves = 16B)
        int gm = m0 + m;
        int ok = (gm < VOCAB) ? 16 : 0;
        const __half* srca = &d_embh[(size_t)gm*304 + k0 + c*8];
        if (gm >= VOCAB) srca = d_embh;
        cp16(sA + (unsigned)(bf*6144 + m*48 + c*16), srca, ok);
        const __half* srcb = &Wg[(size_t)(n0 + m)*304 + k0 + c*8];
        cp16(sB + (unsigned)(bf*6144 + m*48 + c*16), srcb, 16);
        asm volatile("cp.async.commit_group;" ::: "memory");
    };

    float acc[4][4][4] = {};

    load_stage(0, 0);
    for (int it = 0; it < NIT; it++){
        int bf = it & 1;
        if (it + 1 < NIT){
            load_stage(it + 1, bf ^ 1);
            asm volatile("cp.async.wait_group 1;" ::: "memory");
        } else {
            asm volatile("cp.async.wait_group 0;" ::: "memory");
        }
        __syncthreads();

        unsigned a[4][4], b[4][2];
        #pragma unroll
        for (int mi = 0; mi < 4; mi++){
            int r = wm*64 + mi*16 + g;
            a[mi][0] = *(const unsigned*)&As[bf][r    ][2*q];
            a[mi][1] = *(const unsigned*)&As[bf][r + 8][2*q];
            a[mi][2] = *(const unsigned*)&As[bf][r    ][2*q + 8];
            a[mi][3] = *(const unsigned*)&As[bf][r + 8][2*q + 8];
        }
        #pragma unroll
        for (int ni = 0; ni < 4; ni++){
            int n = wn*32 + ni*8 + g;
            b[ni][0] = *(const unsigned*)&Bs[bf][n][2*q];
            b[ni][1] = *(const unsigned*)&Bs[bf][n][2*q + 8];
        }
        #pragma unroll
        for (int mi = 0; mi < 4; mi++)
            #pragma unroll
            for (int ni = 0; ni < 4; ni++)
                asm volatile(
                    "mma.sync.aligned.m16n8k16.row.col.f32.f16.f16.f32 "
                    "{%0,%1,%2,%3},{%4,%5,%6,%7},{%8,%9},{%0,%1,%2,%3};"
                    : "+f"(acc[mi][ni][0]), "+f"(acc[mi][ni][1]),
                      "+f"(acc[mi][ni][2]), "+f"(acc[mi][ni][3])
                    : "r"(a[mi][0]), "r"(a[mi][1]), "r"(a[mi][2]), "r"(a[mi][3]),
                      "r"(b[ni][0]), "r"(b[ni][1]));
        __syncthreads();
    }

    #pragma unroll
    for (int mi = 0; mi < 4; mi++){
        int rbase = m0 + wm*64 + mi*16 + g;
        #pragma unroll
        for (int ni = 0; ni < 4; ni++){
            int cbase = n0 + wn*32 + ni*8 + q*2;
            #pragma unroll
            for (int c = 0; c < 4; c++){
                int gm  = rbase + (c >> 1)*8;
                int col = cbase + (c & 1);
                if (gm >= VOCAB) continue;
                int gg = col >> 8;
                int hc = col & 255;
                d_proj[gm][dir*GATES + hc*4 + gg] = acc[mi][ni][c] + bg[col];
            }
        }
    }
}

// ---------------------------------------------------------------------------
// Kernel 3: persistent bidirectional LSTM — EXACT R11 (2445.6us-proven):
// cluster(4), barrier.cluster per step, full staging, single MMA loop.
// ---------------------------------------------------------------------------
__global__ void __launch_bounds__(256, 1) __cluster_dims__(4, 1, 1)
k_rnn(const float* __restrict__ Wfw, const float* __restrict__ Wbw,
      const int* __restrict__ ids){
    extern __shared__ unsigned smem_u[];
    unsigned* sWb = smem_u;            // 2 regions x [wg 0..7][kb][lane] uint4 fp16 B frags
    unsigned* sh2 = smem_u + 32768;    // [16][132] fp16 pairs, k-permuted

    int tid = threadIdx.x;
    int bid = blockIdx.x;
    int dir = bid >> 6;
    int tl  = bid & 63;
    int b0  = (tl >> 2) * 16;          // batch tile (16 rows)
    int h0  = (tl & 3) * 64;           // hid tile (64 cols) == cluster rank * 64
    const float* __restrict__ Wg = dir ? Wbw : Wfw;

    int lane = tid & 31;
    int wg   = tid >> 5;    // warp id = hid group of 8 (0..7)
    int gid  = lane >> 2;
    int qq   = lane & 3;

    // ---- Fill Wh fp16 B-fragments once, uint4-packed per (wg,kb,lane) ----
    for (int f = tid; f < 32768; f += 256){
        int s   = f & 1;
        int gg  = (f >> 1) & 1;
        int ln  = (f >> 2) & 31;
        int kb  = (f >> 7) & 15;
        int wgf = (f >> 11) & 7;
        int r   = (f >> 14) & 1;
        int g   = r*2 + gg;
        int k   = kb*16 + (ln & 3)*2 + s*8;
        int col = g*HID + h0 + wgf*8 + (ln >> 2);
        sWb[r*16384 + ((wgf*16 + kb)*32 + ln)*4 + gg*2 + s] =
            packh2(Wg[(EMB + k)*GATES + col], Wg[(EMB + k + 1)*GATES + col]);
    }

    int rb0 = gid;              // block-local batch rows this thread owns
    int rb1 = gid + 8;
    int hc0 = wg*8 + qq*2;      // block-local hidden cols (one fp16 pair), 0..63
    int len0 = d_len[b0 + rb0];
    int len1 = d_len[b0 + rb1];
    float c_reg[4] = {0.f,0.f,0.f,0.f};
    float h_reg[4] = {0.f,0.f,0.f,0.f};
    int   wslot = hslot(h0 + hc0);

    // prefetch xz for t=0
    const int row0 = (b0 + rb0)*SEQT;
    const int row1 = (b0 + rb1)*SEQT;
    float4 xzn0, xzn1, xzn2, xzn3;
    {
        int teff = dir ? (SEQT - 1) : 0;
        int id0 = __ldg(&ids[row0 + teff]);
        int id1 = __ldg(&ids[row1 + teff]);
        const float* p0 = &d_proj[id0][dir*GATES];
        const float* p1 = &d_proj[id1][dir*GATES];
        xzn0 = *(const float4*)&p0[(h0 + hc0    )*4];
        xzn1 = *(const float4*)&p0[(h0 + hc0 + 1)*4];
        xzn2 = *(const float4*)&p1[(h0 + hc0    )*4];
        xzn3 = *(const float4*)&p1[(h0 + hc0 + 1)*4];
    }

    asm volatile("barrier.cluster.arrive.aligned;" ::: "memory");

    for (int t = 0; t < SEQT; t++){
        int cur = t & 1, nxt = cur ^ 1;
        int teff = dir ? (SEQT - 1 - t) : t;

        asm volatile("barrier.cluster.wait.aligned;" ::: "memory");

        // stage current h: flat contiguous copy (16 rows x 132 u32 = 528 uint4)
        {
            const uint4* src = (const uint4*)&d_hbuf[dir][cur][b0][0];
            uint4* dst = (uint4*)sh2;
            dst[tid]       = __ldcg(&src[tid]);
            dst[tid + 256] = __ldcg(&src[tid + 256]);
            if (tid < 16) dst[tid + 512] = __ldcg(&src[tid + 512]);
        }
        __syncthreads();

        // accumulators initialized with prefetched xz (bias + input projection)
        float acc[4][4];
        acc[0][0]=xzn0.x; acc[1][0]=xzn0.y; acc[2][0]=xzn0.z; acc[3][0]=xzn0.w;
        acc[0][1]=xzn1.x; acc[1][1]=xzn1.y; acc[2][1]=xzn1.z; acc[3][1]=xzn1.w;
        acc[0][2]=xzn2.x; acc[1][2]=xzn2.y; acc[2][2]=xzn2.z; acc[3][2]=xzn2.w;
        acc[0][3]=xzn3.x; acc[1][3]=xzn3.y; acc[2][3]=xzn3.z; acc[3][3]=xzn3.w;

        #pragma unroll
        for (int kb = 0; kb < 16; kb++){
            uint2 aA = *(const uint2*)&sh2[rb0*132 + kb*8 + qq*2];
            uint2 aB = *(const uint2*)&sh2[rb1*132 + kb*8 + qq*2];
            uint4 B01 = *(const uint4*)&sWb[        ((wg*16 + kb)*32 + lane)*4];
            uint4 B23 = *(const uint4*)&sWb[16384 + ((wg*16 + kb)*32 + lane)*4];
            asm volatile(
                "mma.sync.aligned.m16n8k16.row.col.f32.f16.f16.f32 "
                "{%0,%1,%2,%3},{%4,%5,%6,%7},{%8,%9},{%0,%1,%2,%3};"
                : "+f"(acc[0][0]), "+f"(acc[0][1]), "+f"(acc[0][2]), "+f"(acc[0][3])
                : "r"(aA.x), "r"(aB.x), "r"(aA.y), "r"(aB.y), "r"(B01.x), "r"(B01.y));
            asm volatile(
                "mma.sync.aligned.m16n8k16.row.col.f32.f16.f16.f32 "
                "{%0,%1,%2,%3},{%4,%5,%6,%7},{%8,%9},{%0,%1,%2,%3};"
                : "+f"(acc[1][0]), "+f"(acc[1][1]), "+f"(acc[1][2]), "+f"(acc[1][3])
                : "r"(aA.x), "r"(aB.x), "r"(aA.y), "r"(aB.y), "r"(B01.z), "r"(B01.w));
            asm volatile(
                "mma.sync.aligned.m16n8k16.row.col.f32.f16.f16.f32 "
                "{%0,%1,%2,%3},{%4,%5,%6,%7},{%8,%9},{%0,%1,%2,%3};"
                : "+f"(acc[2][0]), "+f"(acc[2][1]), "+f"(acc[2][2]), "+f"(acc[2][3])
                : "r"(aA.x), "r"(aB.x), "r"(aA.y), "r"(aB.y), "r"(B23.x), "r"(B23.y));
            asm volatile(
                "mma.sync.aligned.m16n8k16.row.col.f32.f16.f16.f32 "
                "{%0,%1,%2,%3},{%4,%5,%6,%7},{%8,%9},{%0,%1,%2,%3};"
                : "+f"(acc[3][0]), "+f"(acc[3][1]), "+f"(acc[3][2]), "+f"(acc[3][3])
                : "r"(aA.x), "r"(aB.x), "r"(aA.y), "r"(aB.y), "r"(B23.z), "r"(B23.w));
        }

        // elementwise LSTM cell (tanh.approx activations)
        {
            bool v0 = (teff < len0);
            bool v1 = (teff < len1);
            #pragma unroll
            for (int ci = 0; ci < 4; ci++){
                float zi = acc[0][ci], zj = acc[1][ci];
                float zf = acc[2][ci], zo = acc[3][ci];
                float nc = c_reg[ci]*sigt(zf + 1.0f) + sigt(zi)*tanha(zj);
                float nh = tanha(nc)*sigt(zo);
                bool v = (ci < 2) ? v0 : v1;
                if (v){ c_reg[ci] = nc; h_reg[ci] = nh; }
            }
        }

        // write new h pairs to the global exchange buffer (L2)
        d_hbuf[dir][nxt][b0 + rb0][wslot] = packh2(h_reg[0], h_reg[1]);
        d_hbuf[dir][nxt][b0 + rb1][wslot] = packh2(h_reg[2], h_reg[3]);

        // prefetch next step's xz (flies under barrier + next stage + MMA)
        if (t + 1 < SEQT){
            int tn = dir ? (SEQT - 2 - t) : (t + 1);
            int id0 = __ldg(&ids[row0 + tn]);
            int id1 = __ldg(&ids[row1 + tn]);
            const float* p0 = &d_proj[id0][dir*GATES];
            const float* p1 = &d_proj[id1][dir*GATES];
            xzn0 = *(const float4*)&p0[(h0 + hc0    )*4];
            xzn1 = *(const float4*)&p0[(h0 + hc0 + 1)*4];
            xzn2 = *(const float4*)&p1[(h0 + hc0    )*4];
            xzn3 = *(const float4*)&p1[(h0 + hc0 + 1)*4];
        }

        asm volatile("barrier.cluster.arrive.aligned;" ::: "memory");
    }
    asm volatile("barrier.cluster.wait.aligned;" ::: "memory");

    // write fp32 final hidden state
    d_hfinal[dir][b0 + rb0][h0 + hc0    ] = h_reg[0];
    d_hfinal[dir][b0 + rb0][h0 + hc0 + 1] = h_reg[1];
    d_hfinal[dir][b0 + rb1][h0 + hc0    ] = h_reg[2];
    d_hfinal[dir][b0 + rb1][h0 + hc0 + 1] = h_reg[3];
}

// ---------------------------------------------------------------------------
// Kernel 4: final projection scores = [h_fw | h_bw] @ W_out + b_out
// ---------------------------------------------------------------------------
__global__ void k_out(const float* __restrict__ Wout, const float* __restrict__ bout,
                      float* __restrict__ out){
    int b = blockIdx.x;
    int tid = threadIdx.x;
    float s0 = 0.0f, s1 = 0.0f;
    for (int k = tid; k < 512; k += 256){
        float v = (k < 256) ? d_hfinal[0][b][k] : d_hfinal[1][b][k - 256];
        s0 += v*Wout[2*k];
        s1 += v*Wout[2*k + 1];
    }
    #pragma unroll
    for (int o = 16; o; o >>= 1){
        s0 += __shfl_down_sync(0xffffffffu, s0, o);
        s1 += __shfl_down_sync(0xffffffffu, s1, o);
    }
    __shared__ float r0[8], r1[8];
    int w = tid >> 5;
    if ((tid & 31) == 0){ r0[w] = s0; r1[w] = s1; }
    __syncthreads();
    if (tid == 0){
        float t0 = bout[0], t1 = bout[1];
        #pragma unroll
        for (int i = 0; i < 8; i++){ t0 += r0[i]; t1 += r1[i]; }
        out[2*b]     = t0;
        out[2*b + 1] = t1;
    }
}

// ---------------------------------------------------------------------------
extern "C" void kernel_launch(void* const* d_in, const int* in_sizes, int n_in,
                              void* d_out, int out_size){
    const int*   ids  = (const int*)  d_in[0];
    const float* emb  = (const float*)d_in[1];
    const float* Wfw  = (const float*)d_in[2];
    const float* bfw  = (const float*)d_in[3];
    const float* Wbw  = (const float*)d_in[4];
    const float* bbw  = (const float*)d_in[5];
    const float* Wout = (const float*)d_in[6];
    const float* bout = (const float*)d_in[7];
    float* out = (float*)d_out;

    cudaFuncSetAttribute(k_rnn, cudaFuncAttributeMaxDynamicSharedMemorySize, SMEM_RNN);

    k_init<<<BATCH, 128>>>(ids);
    k_cvt_emb<<<(VOCAB*76 + 255)/256, 256>>>(emb);
    k_cvt_w<<<(2*GATES*76 + 255)/256, 256>>>(Wfw, Wbw);
    dim3 g2(16, (VOCAB + 127)/128);
    k_vgemm<<<g2, 256>>>(bfw, bbw);
    k_rnn<<<NBLK, 256, SMEM_RNN>>>(Wfw, Wbw, ids);
    k_out<<<BATCH, 256>>>(Wout, bout, out);
}

// round 15
// speedup vs baseline: 1.1641x; 1.0223x over previous
#include <cuda_runtime.h>
#include <cuda_fp16.h>
#include <math.h>

#define BATCH 256
#define SEQT  512
#define VOCAB 50000
#define EMB   300
#define HID   256
#define GATES 1024   // 4*HID
#define NBLK  128
// sWb (32768 u32) + sh2 (16*132 u32)
#define SMEM_RNN (32768*4 + 2112*4)

// Scratch (static device memory — allocation-free)
__device__ float    d_proj[VOCAB][2*GATES];    // [v][dir*1024 + hc*4 + g], bias folded in
__device__ unsigned d_hbuf[2][2][BATCH][132];  // fp16 pairs, k-permuted
__device__ float    d_hfinal[2][BATCH][HID];   // fp32 final hidden state
__device__ int      d_len[BATCH];
__device__ __half   d_embh[(size_t)VOCAB*304];     // fp16 emb, k padded to 304
__device__ __half   d_wxh[(size_t)2*GATES*304];    // fp16 Wx, n-major: [dir*1024+n][k]

__device__ __forceinline__ float tanha(float x){
    float y; asm("tanh.approx.f32 %0, %1;" : "=f"(y) : "f"(x)); return y;
}
__device__ __forceinline__ float sigt(float x){
    return fmaf(tanha(0.5f*x), 0.5f, 0.5f);
}
// pair-permutation inside a 16-k block: pair j -> slot (j&3)*2 + (j>>2)
__device__ __forceinline__ int hslot(int k){   // k even; returns u32 index
    int blk = k >> 4, j = (k & 15) >> 1;
    return blk*8 + (j & 3)*2 + (j >> 2);
}
__device__ __forceinline__ unsigned packh2(float a, float b){
    __half2 hv = __halves2half2(__float2half_rn(a), __float2half_rn(b));
    return *(unsigned*)&hv;
}
__device__ __forceinline__ void cp16(unsigned dst_smem, const void* src, int szbytes){
    asm volatile("cp.async.cg.shared.global [%0], [%1], 16, %2;"
                 :: "r"(dst_smem), "l"(src), "r"(szbytes));
}
__device__ __forceinline__ void ldsm4(unsigned& r0, unsigned& r1, unsigned& r2,
                                      unsigned& r3, unsigned addr){
    asm volatile("ldmatrix.sync.aligned.m8n8.x4.shared.b16 {%0,%1,%2,%3}, [%4];"
                 : "=r"(r0), "=r"(r1), "=r"(r2), "=r"(r3) : "r"(addr));
}

// ---------------------------------------------------------------------------
// Kernel 1: lengths + zero initial (permuted-fp16) h states
// ---------------------------------------------------------------------------
__global__ void k_init(const int* __restrict__ ids){
    int b = blockIdx.x;
    __shared__ int cnt;
    if (threadIdx.x == 0) cnt = 0;
    __syncthreads();
    int c = 0;
    for (int t = threadIdx.x; t < SEQT; t += blockDim.x)
        c += (ids[b*SEQT + t] != 0);
    #pragma unroll
    for (int o = 16; o; o >>= 1) c += __shfl_down_sync(0xffffffffu, c, o);
    if ((threadIdx.x & 31) == 0) atomicAdd(&cnt, c);
    __syncthreads();
    if (threadIdx.x == 0) d_len[b] = cnt;
    for (int i = threadIdx.x; i < 132; i += blockDim.x){
        d_hbuf[0][0][b][i] = 0u;
        d_hbuf[0][1][b][i] = 0u;
        d_hbuf[1][0][b][i] = 0u;
        d_hbuf[1][1][b][i] = 0u;
    }
}

// ---------------------------------------------------------------------------
// Kernel 1b: one-shot fp16 conversions
// ---------------------------------------------------------------------------
__global__ void k_cvt_emb(const float* __restrict__ emb){
    int idx = blockIdx.x*blockDim.x + threadIdx.x;   // over VOCAB*76
    if (idx >= VOCAB*76) return;
    int v  = idx / 76;
    int k4 = (idx % 76)*4;
    __half2 h0, h1;
    if (k4 < EMB){
        float4 f = *(const float4*)&emb[(size_t)v*EMB + k4];
        h0 = __floats2half2_rn(f.x, f.y);
        h1 = __floats2half2_rn(f.z, f.w);
    } else {
        h0 = __floats2half2_rn(0.f, 0.f);
        h1 = h0;
    }
    *(__half2*)&d_embh[(size_t)v*304 + k4    ] = h0;
    *(__half2*)&d_embh[(size_t)v*304 + k4 + 2] = h1;
}

__global__ void k_cvt_w(const float* __restrict__ Wfw, const float* __restrict__ Wbw){
    int idx = blockIdx.x*blockDim.x + threadIdx.x;   // over 2*1024*76
    if (idx >= 2*GATES*76) return;
    int dir = idx / (GATES*76);
    int r   = idx % (GATES*76);
    int n   = r / 76;
    int k4  = (r % 76)*4;
    const float* W = dir ? Wbw : Wfw;
    float f0=0.f, f1=0.f, f2=0.f, f3=0.f;
    if (k4 < EMB){
        f0 = W[(k4    )*GATES + n];
        f1 = W[(k4 + 1)*GATES + n];
        f2 = W[(k4 + 2)*GATES + n];
        f3 = W[(k4 + 3)*GATES + n];
    }
    size_t o = ((size_t)dir*GATES + n)*304 + k4;
    *(__half2*)&d_wxh[o    ] = __floats2half2_rn(f0, f1);
    *(__half2*)&d_wxh[o + 2] = __floats2half2_rn(f2, f3);
}

// ---------------------------------------------------------------------------
// Kernel 2: vocab projection GEMM via fp16 m16n8k16 mma.
// 3-stage cp.async ring (ONE __syncthreads per k-tile) + ldmatrix.x4 fragment
// loads (6 LDSM replace 24 LDS.32 per thread per tile). A: [m][24] halves,
// B: [n][24] halves (n-major). fp32 accumulate; bias in fp32 epilogue.
// ---------------------------------------------------------------------------
#define NIT 19          // 304/16
#define VBUF 6144       // bytes per A (or B) stage buffer: 128*48
__global__ void __launch_bounds__(256, 2)
k_vgemm(const float* __restrict__ bfw, const float* __restrict__ bbw){
    __shared__ __half As[3][128][24];    // 48B rows
    __shared__ __half Bs[3][128][24];
    int nx  = blockIdx.x;
    int dir = nx >> 3;
    int n0  = (nx & 7) * 128;
    int m0  = blockIdx.y * 128;
    const float*  __restrict__ bg = dir ? bbw : bfw;
    const __half* __restrict__ Wg = d_wxh + (size_t)dir*GATES*304;

    int t    = threadIdx.x;
    int lane = t & 31;
    int w    = t >> 5;
    int wm   = w & 1;
    int wn   = w >> 1;
    int q    = lane & 3;
    int g    = lane >> 2;

    unsigned sA = (unsigned)__cvta_generic_to_shared(&As[0][0][0]);
    unsigned sB = (unsigned)__cvta_generic_to_shared(&Bs[0][0][0]);

    // per-lane static ldmatrix addresses (add bf*VBUF per stage)
    int mi4 = lane >> 3;        // matrix index within x4
    int ri  = lane & 7;         // row within matrix
    unsigned offA[4], offB[2];
    #pragma unroll
    for (int mi = 0; mi < 4; mi++){
        int row = wm*64 + mi*16 + (mi4 & 1)*8 + ri;
        offA[mi] = sA + (unsigned)(row*48 + (mi4 >> 1)*16);
    }
    #pragma unroll
    for (int j = 0; j < 2; j++){
        int n = wn*32 + j*16 + (mi4 >> 1)*8 + ri;
        offB[j] = sB + (unsigned)(n*48 + (mi4 & 1)*16);
    }

    // async-load one 16-k stage into buffer bf (1 A-chunk + 1 B-chunk/thread)
    auto load_stage = [&](int it, int bf){
        int k0 = it*16;
        int m  = t >> 1;           // 0..127
        int c  = t & 1;            // chunk (8 halves = 16B)
        int gm = m0 + m;
        int ok = (gm < VOCAB) ? 16 : 0;
        const __half* srca = &d_embh[(size_t)gm*304 + k0 + c*8];
        if (gm >= VOCAB) srca = d_embh;
        cp16(sA + (unsigned)(bf*VBUF + m*48 + c*16), srca, ok);
        const __half* srcb = &Wg[(size_t)(n0 + m)*304 + k0 + c*8];
        cp16(sB + (unsigned)(bf*VBUF + m*48 + c*16), srcb, 16);
        asm volatile("cp.async.commit_group;" ::: "memory");
    };

    float acc[4][4][4] = {};

    load_stage(0, 0);
    load_stage(1, 1);
    #pragma unroll 1
    for (int it = 0; it < NIT; it++){
        int bf = it % 3;
        if (it + 1 < NIT)
            asm volatile("cp.async.wait_group 1;" ::: "memory");
        else
            asm volatile("cp.async.wait_group 0;" ::: "memory");
        __syncthreads();
        // issue stage it+2 into buffer (it+2)%3 (its readers finished at it-1)
        if (it + 2 < NIT) load_stage(it + 2, (it + 2) % 3);

        unsigned bo = (unsigned)(bf*VBUF);
        unsigned a[4][4], b[4][2];
        #pragma unroll
        for (int mi = 0; mi < 4; mi++)
            ldsm4(a[mi][0], a[mi][1], a[mi][2], a[mi][3], offA[mi] + bo);
        ldsm4(b[0][0], b[0][1], b[1][0], b[1][1], offB[0] + bo);
        ldsm4(b[2][0], b[2][1], b[3][0], b[3][1], offB[1] + bo);

        #pragma unroll
        for (int mi = 0; mi < 4; mi++)
            #pragma unroll
            for (int ni = 0; ni < 4; ni++)
                asm volatile(
                    "mma.sync.aligned.m16n8k16.row.col.f32.f16.f16.f32 "
                    "{%0,%1,%2,%3},{%4,%5,%6,%7},{%8,%9},{%0,%1,%2,%3};"
                    : "+f"(acc[mi][ni][0]), "+f"(acc[mi][ni][1]),
                      "+f"(acc[mi][ni][2]), "+f"(acc[mi][ni][3])
                    : "r"(a[mi][0]), "r"(a[mi][1]), "r"(a[mi][2]), "r"(a[mi][3]),
                      "r"(b[ni][0]), "r"(b[ni][1]));
    }

    #pragma unroll
    for (int mi = 0; mi < 4; mi++){
        int rbase = m0 + wm*64 + mi*16 + g;
        #pragma unroll
        for (int ni = 0; ni < 4; ni++){
            int cbase = n0 + wn*32 + ni*8 + q*2;
            #pragma unroll
            for (int c = 0; c < 4; c++){
                int gm  = rbase + (c >> 1)*8;
                int col = cbase + (c & 1);
                if (gm >= VOCAB) continue;
                int gg = col >> 8;
                int hc = col & 255;
                d_proj[gm][dir*GATES + hc*4 + gg] = acc[mi][ni][c] + bg[col];
            }
        }
    }
}

// ---------------------------------------------------------------------------
// Kernel 3: persistent bidirectional LSTM — EXACT R11 (proven):
// cluster(4), barrier.cluster per step, full staging, single MMA loop.
// ---------------------------------------------------------------------------
__global__ void __launch_bounds__(256, 1) __cluster_dims__(4, 1, 1)
k_rnn(const float* __restrict__ Wfw, const float* __restrict__ Wbw,
      const int* __restrict__ ids){
    extern __shared__ unsigned smem_u[];
    unsigned* sWb = smem_u;            // 2 regions x [wg 0..7][kb][lane] uint4 fp16 B frags
    unsigned* sh2 = smem_u + 32768;    // [16][132] fp16 pairs, k-permuted

    int tid = threadIdx.x;
    int bid = blockIdx.x;
    int dir = bid >> 6;
    int tl  = bid & 63;
    int b0  = (tl >> 2) * 16;          // batch tile (16 rows)
    int h0  = (tl & 3) * 64;           // hid tile (64 cols) == cluster rank * 64
    const float* __restrict__ Wg = dir ? Wbw : Wfw;

    int lane = tid & 31;
    int wg   = tid >> 5;    // warp id = hid group of 8 (0..7)
    int gid  = lane >> 2;
    int qq   = lane & 3;

    // ---- Fill Wh fp16 B-fragments once, uint4-packed per (wg,kb,lane) ----
    for (int f = tid; f < 32768; f += 256){
        int s   = f & 1;
        int gg  = (f >> 1) & 1;
        int ln  = (f >> 2) & 31;
        int kb  = (f >> 7) & 15;
        int wgf = (f >> 11) & 7;
        int r   = (f >> 14) & 1;
        int g   = r*2 + gg;
        int k   = kb*16 + (ln & 3)*2 + s*8;
        int col = g*HID + h0 + wgf*8 + (ln >> 2);
        sWb[r*16384 + ((wgf*16 + kb)*32 + ln)*4 + gg*2 + s] =
            packh2(Wg[(EMB + k)*GATES + col], Wg[(EMB + k + 1)*GATES + col]);
    }

    int rb0 = gid;              // block-local batch rows this thread owns
    int rb1 = gid + 8;
    int hc0 = wg*8 + qq*2;      // block-local hidden cols (one fp16 pair), 0..63
    int len0 = d_len[b0 + rb0];
    int len1 = d_len[b0 + rb1];
    float c_reg[4] = {0.f,0.f,0.f,0.f};
    float h_reg[4] = {0.f,0.f,0.f,0.f};
    int   wslot = hslot(h0 + hc0);

    // prefetch xz for t=0
    const int row0 = (b0 + rb0)*SEQT;
    const int row1 = (b0 + rb1)*SEQT;
    float4 xzn0, xzn1, xzn2, xzn3;
    {
        int teff = dir ? (SEQT - 1) : 0;
        int id0 = __ldg(&ids[row0 + teff]);
        int id1 = __ldg(&ids[row1 + teff]);
        const float* p0 = &d_proj[id0][dir*GATES];
        const float* p1 = &d_proj[id1][dir*GATES];
        xzn0 = *(const float4*)&p0[(h0 + hc0    )*4];
        xzn1 = *(const float4*)&p0[(h0 + hc0 + 1)*4];
        xzn2 = *(const float4*)&p1[(h0 + hc0    )*4];
        xzn3 = *(const float4*)&p1[(h0 + hc0 + 1)*4];
    }

    asm volatile("barrier.cluster.arrive.aligned;" ::: "memory");

    for (int t = 0; t < SEQT; t++){
        int cur = t & 1, nxt = cur ^ 1;
        int teff = dir ? (SEQT - 1 - t) : t;

        asm volatile("barrier.cluster.wait.aligned;" ::: "memory");

        // stage current h: flat contiguous copy (16 rows x 132 u32 = 528 uint4)
        {
            const uint4* src = (const uint4*)&d_hbuf[dir][cur][b0][0];
            uint4* dst = (uint4*)sh2;
            dst[tid]       = __ldcg(&src[tid]);
            dst[tid + 256] = __ldcg(&src[tid + 256]);
            if (tid < 16) dst[tid + 512] = __ldcg(&src[tid + 512]);
        }
        __syncthreads();

        // accumulators initialized with prefetched xz (bias + input projection)
        float acc[4][4];
        acc[0][0]=xzn0.x; acc[1][0]=xzn0.y; acc[2][0]=xzn0.z; acc[3][0]=xzn0.w;
        acc[0][1]=xzn1.x; acc[1][1]=xzn1.y; acc[2][1]=xzn1.z; acc[3][1]=xzn1.w;
        acc[0][2]=xzn2.x; acc[1][2]=xzn2.y; acc[2][2]=xzn2.z; acc[3][2]=xzn2.w;
        acc[0][3]=xzn3.x; acc[1][3]=xzn3.y; acc[2][3]=xzn3.z; acc[3][3]=xzn3.w;

        #pragma unroll
        for (int kb = 0; kb < 16; kb++){
            uint2 aA = *(const uint2*)&sh2[rb0*132 + kb*8 + qq*2];
            uint2 aB = *(const uint2*)&sh2[rb1*132 + kb*8 + qq*2];
            uint4 B01 = *(const uint4*)&sWb[        ((wg*16 + kb)*32 + lane)*4];
            uint4 B23 = *(const uint4*)&sWb[16384 + ((wg*16 + kb)*32 + lane)*4];
            asm volatile(
                "mma.sync.aligned.m16n8k16.row.col.f32.f16.f16.f32 "
                "{%0,%1,%2,%3},{%4,%5,%6,%7},{%8,%9},{%0,%1,%2,%3};"
                : "+f"(acc[0][0]), "+f"(acc[0][1]), "+f"(acc[0][2]), "+f"(acc[0][3])
                : "r"(aA.x), "r"(aB.x), "r"(aA.y), "r"(aB.y), "r"(B01.x), "r"(B01.y));
            asm volatile(
                "mma.sync.aligned.m16n8k16.row.col.f32.f16.f16.f32 "
                "{%0,%1,%2,%3},{%4,%5,%6,%7},{%8,%9},{%0,%1,%2,%3};"
                : "+f"(acc[1][0]), "+f"(acc[1][1]), "+f"(acc[1][2]), "+f"(acc[1][3])
                : "r"(aA.x), "r"(aB.x), "r"(aA.y), "r"(aB.y), "r"(B01.z), "r"(B01.w));
            asm volatile(
                "mma.sync.aligned.m16n8k16.row.col.f32.f16.f16.f32 "
                "{%0,%1,%2,%3},{%4,%5,%6,%7},{%8,%9},{%0,%1,%2,%3};"
                : "+f"(acc[2][0]), "+f"(acc[2][1]), "+f"(acc[2][2]), "+f"(acc[2][3])
                : "r"(aA.x), "r"(aB.x), "r"(aA.y), "r"(aB.y), "r"(B23.x), "r"(B23.y));
            asm volatile(
                "mma.sync.aligned.m16n8k16.row.col.f32.f16.f16.f32 "
                "{%0,%1,%2,%3},{%4,%5,%6,%7},{%8,%9},{%0,%1,%2,%3};"
                : "+f"(acc[3][0]), "+f"(acc[3][1]), "+f"(acc[3][2]), "+f"(acc[3][3])
                : "r"(aA.x), "r"(aB.x), "r"(aA.y), "r"(aB.y), "r"(B23.z), "r"(B23.w));
        }

        // elementwise LSTM cell (tanh.approx activations)
        {
            bool v0 = (teff < len0);
            bool v1 = (teff < len1);
            #pragma unroll
            for (int ci = 0; ci < 4; ci++){
                float zi = acc[0][ci], zj = acc[1][ci];
                float zf = acc[2][ci], zo = acc[3][ci];
                float nc = c_reg[ci]*sigt(zf + 1.0f) + sigt(zi)*tanha(zj);
                float nh = tanha(nc)*sigt(zo);
                bool v = (ci < 2) ? v0 : v1;
                if (v){ c_reg[ci] = nc; h_reg[ci] = nh; }
            }
        }

        // write new h pairs to the global exchange buffer (L2)
        d_hbuf[dir][nxt][b0 + rb0][wslot] = packh2(h_reg[0], h_reg[1]);
        d_hbuf[dir][nxt][b0 + rb1][wslot] = packh2(h_reg[2], h_reg[3]);

        // prefetch next step's xz (flies under barrier + next stage + MMA)
        if (t + 1 < SEQT){
            int tn = dir ? (SEQT - 2 - t) : (t + 1);
            int id0 = __ldg(&ids[row0 + tn]);
            int id1 = __ldg(&ids[row1 + tn]);
            const float* p0 = &d_proj[id0][dir*GATES];
            const float* p1 = &d_proj[id1][dir*GATES];
            xzn0 = *(const float4*)&p0[(h0 + hc0    )*4];
            xzn1 = *(const float4*)&p0[(h0 + hc0 + 1)*4];
            xzn2 = *(const float4*)&p1[(h0 + hc0    )*4];
            xzn3 = *(const float4*)&p1[(h0 + hc0 + 1)*4];
        }

        asm volatile("barrier.cluster.arrive.aligned;" ::: "memory");
    }
    asm volatile("barrier.cluster.wait.aligned;" ::: "memory");

    // write fp32 final hidden state
    d_hfinal[dir][b0 + rb0][h0 + hc0    ] = h_reg[0];
    d_hfinal[dir][b0 + rb0][h0 + hc0 + 1] = h_reg[1];
    d_hfinal[dir][b0 + rb1][h0 + hc0    ] = h_reg[2];
    d_hfinal[dir][b0 + rb1][h0 + hc0 + 1] = h_reg[3];
}

// ---------------------------------------------------------------------------
// Kernel 4: final projection scores = [h_fw | h_bw] @ W_out + b_out
// ---------------------------------------------------------------------------
__global__ void k_out(const float* __restrict__ Wout, const float* __restrict__ bout,
                      float* __restrict__ out){
    int b = blockIdx.x;
    int tid = threadIdx.x;
    float s0 = 0.0f, s1 = 0.0f;
    for (int k = tid; k < 512; k += 256){
        float v = (k < 256) ? d_hfinal[0][b][k] : d_hfinal[1][b][k - 256];
        s0 += v*Wout[2*k];
        s1 += v*Wout[2*k + 1];
    }
    #pragma unroll
    for (int o = 16; o; o >>= 1){
        s0 += __shfl_down_sync(0xffffffffu, s0, o);
        s1 += __shfl_down_sync(0xffffffffu, s1, o);
    }
    __shared__ float r0[8], r1[8];
    int w = tid >> 5;
    if ((tid & 31) == 0){ r0[w] = s0; r1[w] = s1; }
    __syncthreads();
    if (tid == 0){
        float t0 = bout[0], t1 = bout[1];
        #pragma unroll
        for (int i = 0; i < 8; i++){ t0 += r0[i]; t1 += r1[i]; }
        out[2*b]     = t0;
        out[2*b + 1] = t1;
    }
}

// ---------------------------------------------------------------------------
extern "C" void kernel_launch(void* const* d_in, const int* in_sizes, int n_in,
                              void* d_out, int out_size){
    const int*   ids  = (const int*)  d_in[0];
    const float* emb  = (const float*)d_in[1];
    const float* Wfw  = (const float*)d_in[2];
    const float* bfw  = (const float*)d_in[3];
    const float* Wbw  = (const float*)d_in[4];
    const float* bbw  = (const float*)d_in[5];
    const float* Wout = (const float*)d_in[6];
    const float* bout = (const float*)d_in[7];
    float* out = (float*)d_out;

    cudaFuncSetAttribute(k_rnn, cudaFuncAttributeMaxDynamicSharedMemorySize, SMEM_RNN);

    k_init<<<BATCH, 128>>>(ids);
    k_cvt_emb<<<(VOCAB*76 + 255)/256, 256>>>(emb);
    k_cvt_w<<<(2*GATES*76 + 255)/256, 256>>>(Wfw, Wbw);
    dim3 g2(16, (VOCAB + 127)/128);
    k_vgemm<<<g2, 256>>>(bfw, bbw);
    k_rnn<<<NBLK, 256, SMEM_RNN>>>(Wfw, Wbw, ids);
    k_out<<<BATCH, 256>>>(Wout, bout, out);
}

// round 16
// speedup vs baseline: 1.3134x; 1.1282x over previous
#include <cuda_runtime.h>
#include <cuda_fp16.h>
#include <math.h>

#define BATCH 256
#define SEQT  512
#define VOCAB 50000
#define EMB   300
#define HID   256
#define GATES 1024   // 4*HID
#define NBLK  128
// sWb (32768 u32) + sh2 (16*132 u32)
#define SMEM_RNN (32768*4 + 2112*4)

// Scratch (static device memory — allocation-free)
__device__ float    d_proj[VOCAB][2*GATES];    // [v][dir*1024 + hc*4 + g], bias folded in
__device__ unsigned d_hbuf[2][2][BATCH][132];  // fp16 pairs, k-permuted
__device__ float    d_hfinal[2][BATCH][HID];   // fp32 final hidden state
__device__ int      d_len[BATCH];
__device__ __half   d_embh[(size_t)VOCAB*304];     // fp16 emb, k padded to 304
// fp16 Wx, n-major AND n-permuted: row n' holds original column (n'&3)*256 + (n'>>2)
// so GEMM column n' lands directly at d_proj slot n' (= hc*4+g interleave).
__device__ __half   d_wxh[(size_t)2*GATES*304];

__device__ __forceinline__ float tanha(float x){
    float y; asm("tanh.approx.f32 %0, %1;" : "=f"(y) : "f"(x)); return y;
}
__device__ __forceinline__ float sigt(float x){
    return fmaf(tanha(0.5f*x), 0.5f, 0.5f);
}
// pair-permutation inside a 16-k block: pair j -> slot (j&3)*2 + (j>>2)
__device__ __forceinline__ int hslot(int k){   // k even; returns u32 index
    int blk = k >> 4, j = (k & 15) >> 1;
    return blk*8 + (j & 3)*2 + (j >> 2);
}
__device__ __forceinline__ unsigned packh2(float a, float b){
    __half2 hv = __halves2half2(__float2half_rn(a), __float2half_rn(b));
    return *(unsigned*)&hv;
}
__device__ __forceinline__ void cp16(unsigned dst_smem, const void* src, int szbytes){
    asm volatile("cp.async.cg.shared.global [%0], [%1], 16, %2;"
                 :: "r"(dst_smem), "l"(src), "r"(szbytes));
}
__device__ __forceinline__ void ldsm4(unsigned& r0, unsigned& r1, unsigned& r2,
                                      unsigned& r3, unsigned addr){
    asm volatile("ldmatrix.sync.aligned.m8n8.x4.shared.b16 {%0,%1,%2,%3}, [%4];"
                 : "=r"(r0), "=r"(r1), "=r"(r2), "=r"(r3) : "r"(addr));
}

// ---------------------------------------------------------------------------
// Kernel 1: lengths + zero initial (permuted-fp16) h states
// ---------------------------------------------------------------------------
__global__ void k_init(const int* __restrict__ ids){
    int b = blockIdx.x;
    __shared__ int cnt;
    if (threadIdx.x == 0) cnt = 0;
    __syncthreads();
    int c = 0;
    for (int t = threadIdx.x; t < SEQT; t += blockDim.x)
        c += (ids[b*SEQT + t] != 0);
    #pragma unroll
    for (int o = 16; o; o >>= 1) c += __shfl_down_sync(0xffffffffu, c, o);
    if ((threadIdx.x & 31) == 0) atomicAdd(&cnt, c);
    __syncthreads();
    if (threadIdx.x == 0) d_len[b] = cnt;
    for (int i = threadIdx.x; i < 132; i += blockDim.x){
        d_hbuf[0][0][b][i] = 0u;
        d_hbuf[0][1][b][i] = 0u;
        d_hbuf[1][0][b][i] = 0u;
        d_hbuf[1][1][b][i] = 0u;
    }
}

// ---------------------------------------------------------------------------
// Kernel 1b: one-shot fp16 conversions
// ---------------------------------------------------------------------------
__global__ void k_cvt_emb(const float* __restrict__ emb){
    int idx = blockIdx.x*blockDim.x + threadIdx.x;   // over VOCAB*76
    if (idx >= VOCAB*76) return;
    int v  = idx / 76;
    int k4 = (idx % 76)*4;
    __half2 h0, h1;
    if (k4 < EMB){
        float4 f = *(const float4*)&emb[(size_t)v*EMB + k4];
        h0 = __floats2half2_rn(f.x, f.y);
        h1 = __floats2half2_rn(f.z, f.w);
    } else {
        h0 = __floats2half2_rn(0.f, 0.f);
        h1 = h0;
    }
    *(__half2*)&d_embh[(size_t)v*304 + k4    ] = h0;
    *(__half2*)&d_embh[(size_t)v*304 + k4 + 2] = h1;
}

__global__ void k_cvt_w(const float* __restrict__ Wfw, const float* __restrict__ Wbw){
    int idx = blockIdx.x*blockDim.x + threadIdx.x;   // over 2*1024*76
    if (idx >= 2*GATES*76) return;
    int dir = idx / (GATES*76);
    int r   = idx % (GATES*76);
    int np  = r / 76;                 // permuted row n'
    int k4  = (r % 76)*4;
    int n   = (np & 3)*256 + (np >> 2);   // original W column
    const float* W = dir ? Wbw : Wfw;
    float f0=0.f, f1=0.f, f2=0.f, f3=0.f;
    if (k4 < EMB){
        f0 = W[(k4    )*GATES + n];
        f1 = W[(k4 + 1)*GATES + n];
        f2 = W[(k4 + 2)*GATES + n];
        f3 = W[(k4 + 3)*GATES + n];
    }
    size_t o = ((size_t)dir*GATES + np)*304 + k4;
    *(__half2*)&d_wxh[o    ] = __floats2half2_rn(f0, f1);
    *(__half2*)&d_wxh[o + 2] = __floats2half2_rn(f2, f3);
}

// ---------------------------------------------------------------------------
// Kernel 2: vocab projection GEMM via fp16 m16n8k16 mma.
// 3-stage cp.async ring + ldmatrix.x4 fragment loads. N axis is pre-permuted
// (d_wxh row n' = interleaved slot), so the epilogue is COALESCED float2
// stores straight into d_proj (no scatter).
// ---------------------------------------------------------------------------
#define NIT 19          // 304/16
#define VBUF 6144       // bytes per A (or B) stage buffer: 128*48
__global__ void __launch_bounds__(256, 2)
k_vgemm(const float* __restrict__ bfw, const float* __restrict__ bbw){
    __shared__ __half As[3][128][24];    // 48B rows
    __shared__ __half Bs[3][128][24];
    int nx  = blockIdx.x;
    int dir = nx >> 3;
    int n0  = (nx & 7) * 128;
    int m0  = blockIdx.y * 128;
    const float*  __restrict__ bg = dir ? bbw : bfw;
    const __half* __restrict__ Wg = d_wxh + (size_t)dir*GATES*304;

    int t    = threadIdx.x;
    int lane = t & 31;
    int w    = t >> 5;
    int wm   = w & 1;
    int wn   = w >> 1;
    int q    = lane & 3;
    int g    = lane >> 2;

    unsigned sA = (unsigned)__cvta_generic_to_shared(&As[0][0][0]);
    unsigned sB = (unsigned)__cvta_generic_to_shared(&Bs[0][0][0]);

    // per-lane static ldmatrix addresses (add bf*VBUF per stage)
    int mi4 = lane >> 3;        // matrix index within x4
    int ri  = lane & 7;         // row within matrix
    unsigned offA[4], offB[2];
    #pragma unroll
    for (int mi = 0; mi < 4; mi++){
        int row = wm*64 + mi*16 + (mi4 & 1)*8 + ri;
        offA[mi] = sA + (unsigned)(row*48 + (mi4 >> 1)*16);
    }
    #pragma unroll
    for (int j = 0; j < 2; j++){
        int n = wn*32 + j*16 + (mi4 >> 1)*8 + ri;
        offB[j] = sB + (unsigned)(n*48 + (mi4 & 1)*16);
    }

    // async-load one 16-k stage into buffer bf (1 A-chunk + 1 B-chunk/thread)
    auto load_stage = [&](int it, int bf){
        int k0 = it*16;
        int m  = t >> 1;           // 0..127
        int c  = t & 1;            // chunk (8 halves = 16B)
        int gm = m0 + m;
        int ok = (gm < VOCAB) ? 16 : 0;
        const __half* srca = &d_embh[(size_t)gm*304 + k0 + c*8];
        if (gm >= VOCAB) srca = d_embh;
        cp16(sA + (unsigned)(bf*VBUF + m*48 + c*16), srca, ok);
        const __half* srcb = &Wg[(size_t)(n0 + m)*304 + k0 + c*8];
        cp16(sB + (unsigned)(bf*VBUF + m*48 + c*16), srcb, 16);
        asm volatile("cp.async.commit_group;" ::: "memory");
    };

    float acc[4][4][4] = {};

    load_stage(0, 0);
    load_stage(1, 1);
    #pragma unroll 1
    for (int it = 0; it < NIT; it++){
        int bf = it % 3;
        if (it + 1 < NIT)
            asm volatile("cp.async.wait_group 1;" ::: "memory");
        else
            asm volatile("cp.async.wait_group 0;" ::: "memory");
        __syncthreads();
        // issue stage it+2 into buffer (it+2)%3 (its readers finished at it-1)
        if (it + 2 < NIT) load_stage(it + 2, (it + 2) % 3);

        unsigned bo = (unsigned)(bf*VBUF);
        unsigned a[4][4], b[4][2];
        #pragma unroll
        for (int mi = 0; mi < 4; mi++)
            ldsm4(a[mi][0], a[mi][1], a[mi][2], a[mi][3], offA[mi] + bo);
        ldsm4(b[0][0], b[0][1], b[1][0], b[1][1], offB[0] + bo);
        ldsm4(b[2][0], b[2][1], b[3][0], b[3][1], offB[1] + bo);

        #pragma unroll
        for (int mi = 0; mi < 4; mi++)
            #pragma unroll
            for (int ni = 0; ni < 4; ni++)
                asm volatile(
                    "mma.sync.aligned.m16n8k16.row.col.f32.f16.f16.f32 "
                    "{%0,%1,%2,%3},{%4,%5,%6,%7},{%8,%9},{%0,%1,%2,%3};"
                    : "+f"(acc[mi][ni][0]), "+f"(acc[mi][ni][1]),
                      "+f"(acc[mi][ni][2]), "+f"(acc[mi][ni][3])
                    : "r"(a[mi][0]), "r"(a[mi][1]), "r"(a[mi][2]), "r"(a[mi][3]),
                      "r"(b[ni][0]), "r"(b[ni][1]));
    }

    // Epilogue: coalesced float2 stores (N axis already in interleaved order).
    // Bias for permuted col n': original col = (n'&3)*256 + (n'>>2).
    float2 bias[4];
    #pragma unroll
    for (int ni = 0; ni < 4; ni++){
        int np = n0 + wn*32 + ni*8 + q*2;
        bias[ni].x = bg[(np & 3)*256 + (np >> 2)];
        bias[ni].y = bg[((np + 1) & 3)*256 + ((np + 1) >> 2)];
    }
    #pragma unroll
    for (int mi = 0; mi < 4; mi++){
        int rbase = m0 + wm*64 + mi*16 + g;
        #pragma unroll
        for (int ni = 0; ni < 4; ni++){
            int np = n0 + wn*32 + ni*8 + q*2;
            #pragma unroll
            for (int h = 0; h < 2; h++){            // row halves (gm, gm+8)
                int gm = rbase + h*8;
                if (gm >= VOCAB) continue;
                float2 v;
                v.x = acc[mi][ni][h*2    ] + bias[ni].x;
                v.y = acc[mi][ni][h*2 + 1] + bias[ni].y;
                *(float2*)&d_proj[gm][dir*GATES + np] = v;
            }
        }
    }
}

// ---------------------------------------------------------------------------
// Kernel 3: persistent bidirectional LSTM — EXACT R11 (proven):
// cluster(4), barrier.cluster per step, full staging, single MMA loop.
// ---------------------------------------------------------------------------
__global__ void __launch_bounds__(256, 1) __cluster_dims__(4, 1, 1)
k_rnn(const float* __restrict__ Wfw, const float* __restrict__ Wbw,
      const int* __restrict__ ids){
    extern __shared__ unsigned smem_u[];
    unsigned* sWb = smem_u;            // 2 regions x [wg 0..7][kb][lane] uint4 fp16 B frags
    unsigned* sh2 = smem_u + 32768;    // [16][132] fp16 pairs, k-permuted

    int tid = threadIdx.x;
    int bid = blockIdx.x;
    int dir = bid >> 6;
    int tl  = bid & 63;
    int b0  = (tl >> 2) * 16;          // batch tile (16 rows)
    int h0  = (tl & 3) * 64;           // hid tile (64 cols) == cluster rank * 64
    const float* __restrict__ Wg = dir ? Wbw : Wfw;

    int lane = tid & 31;
    int wg   = tid >> 5;    // warp id = hid group of 8 (0..7)
    int gid  = lane >> 2;
    int qq   = lane & 3;

    // ---- Fill Wh fp16 B-fragments once, uint4-packed per (wg,kb,lane) ----
    for (int f = tid; f < 32768; f += 256){
        int s   = f & 1;
        int gg  = (f >> 1) & 1;
        int ln  = (f >> 2) & 31;
        int kb  = (f >> 7) & 15;
        int wgf = (f >> 11) & 7;
        int r   = (f >> 14) & 1;
        int g   = r*2 + gg;
        int k   = kb*16 + (ln & 3)*2 + s*8;
        int col = g*HID + h0 + wgf*8 + (ln >> 2);
        sWb[r*16384 + ((wgf*16 + kb)*32 + ln)*4 + gg*2 + s] =
            packh2(Wg[(EMB + k)*GATES + col], Wg[(EMB + k + 1)*GATES + col]);
    }

    int rb0 = gid;              // block-local batch rows this thread owns
    int rb1 = gid + 8;
    int hc0 = wg*8 + qq*2;      // block-local hidden cols (one fp16 pair), 0..63
    int len0 = d_len[b0 + rb0];
    int len1 = d_len[b0 + rb1];
    float c_reg[4] = {0.f,0.f,0.f,0.f};
    float h_reg[4] = {0.f,0.f,0.f,0.f};
    int   wslot = hslot(h0 + hc0);

    // prefetch xz for t=0
    const int row0 = (b0 + rb0)*SEQT;
    const int row1 = (b0 + rb1)*SEQT;
    float4 xzn0, xzn1, xzn2, xzn3;
    {
        int teff = dir ? (SEQT - 1) : 0;
        int id0 = __ldg(&ids[row0 + teff]);
        int id1 = __ldg(&ids[row1 + teff]);
        const float* p0 = &d_proj[id0][dir*GATES];
        const float* p1 = &d_proj[id1][dir*GATES];
        xzn0 = *(const float4*)&p0[(h0 + hc0    )*4];
        xzn1 = *(const float4*)&p0[(h0 + hc0 + 1)*4];
        xzn2 = *(const float4*)&p1[(h0 + hc0    )*4];
        xzn3 = *(const float4*)&p1[(h0 + hc0 + 1)*4];
    }

    asm volatile("barrier.cluster.arrive.aligned;" ::: "memory");

    for (int t = 0; t < SEQT; t++){
        int cur = t & 1, nxt = cur ^ 1;
        int teff = dir ? (SEQT - 1 - t) : t;

        asm volatile("barrier.cluster.wait.aligned;" ::: "memory");

        // stage current h: flat contiguous copy (16 rows x 132 u32 = 528 uint4)
        {
            const uint4* src = (const uint4*)&d_hbuf[dir][cur][b0][0];
            uint4* dst = (uint4*)sh2;
            dst[tid]       = __ldcg(&src[tid]);
            dst[tid + 256] = __ldcg(&src[tid + 256]);
            if (tid < 16) dst[tid + 512] = __ldcg(&src[tid + 512]);
        }
        __syncthreads();

        // accumulators initialized with prefetched xz (bias + input projection)
        float acc[4][4];
        acc[0][0]=xzn0.x; acc[1][0]=xzn0.y; acc[2][0]=xzn0.z; acc[3][0]=xzn0.w;
        acc[0][1]=xzn1.x; acc[1][1]=xzn1.y; acc[2][1]=xzn1.z; acc[3][1]=xzn1.w;
        acc[0][2]=xzn2.x; acc[1][2]=xzn2.y; acc[2][2]=xzn2.z; acc[3][2]=xzn2.w;
        acc[0][3]=xzn3.x; acc[1][3]=xzn3.y; acc[2][3]=xzn3.z; acc[3][3]=xzn3.w;

        #pragma unroll
        for (int kb = 0; kb < 16; kb++){
            uint2 aA = *(const uint2*)&sh2[rb0*132 + kb*8 + qq*2];
            uint2 aB = *(const uint2*)&sh2[rb1*132 + kb*8 + qq*2];
            uint4 B01 = *(const uint4*)&sWb[        ((wg*16 + kb)*32 + lane)*4];
            uint4 B23 = *(const uint4*)&sWb[16384 + ((wg*16 + kb)*32 + lane)*4];
            asm volatile(
                "mma.sync.aligned.m16n8k16.row.col.f32.f16.f16.f32 "
                "{%0,%1,%2,%3},{%4,%5,%6,%7},{%8,%9},{%0,%1,%2,%3};"
                : "+f"(acc[0][0]), "+f"(acc[0][1]), "+f"(acc[0][2]), "+f"(acc[0][3])
                : "r"(aA.x), "r"(aB.x), "r"(aA.y), "r"(aB.y), "r"(B01.x), "r"(B01.y));
            asm volatile(
                "mma.sync.aligned.m16n8k16.row.col.f32.f16.f16.f32 "
                "{%0,%1,%2,%3},{%4,%5,%6,%7},{%8,%9},{%0,%1,%2,%3};"
                : "+f"(acc[1][0]), "+f"(acc[1][1]), "+f"(acc[1][2]), "+f"(acc[1][3])
                : "r"(aA.x), "r"(aB.x), "r"(aA.y), "r"(aB.y), "r"(B01.z), "r"(B01.w));
            asm volatile(
                "mma.sync.aligned.m16n8k16.row.col.f32.f16.f16.f32 "
                "{%0,%1,%2,%3},{%4,%5,%6,%7},{%8,%9},{%0,%1,%2,%3};"
                : "+f"(acc[2][0]), "+f"(acc[2][1]), "+f"(acc[2][2]), "+f"(acc[2][3])
                : "r"(aA.x), "r"(aB.x), "r"(aA.y), "r"(aB.y), "r"(B23.x), "r"(B23.y));
            asm volatile(
                "mma.sync.aligned.m16n8k16.row.col.f32.f16.f16.f32 "
                "{%0,%1,%2,%3},{%4,%5,%6,%7},{%8,%9},{%0,%1,%2,%3};"
                : "+f"(acc[3][0]), "+f"(acc[3][1]), "+f"(acc[3][2]), "+f"(acc[3][3])
                : "r"(aA.x), "r"(aB.x), "r"(aA.y), "r"(aB.y), "r"(B23.z), "r"(B23.w));
        }

        // elementwise LSTM cell (tanh.approx activations)
        {
            bool v0 = (teff < len0);
            bool v1 = (teff < len1);
            #pragma unroll
            for (int ci = 0; ci < 4; ci++){
                float zi = acc[0][ci], zj = acc[1][ci];
                float zf = acc[2][ci], zo = acc[3][ci];
                float nc = c_reg[ci]*sigt(zf + 1.0f) + sigt(zi)*tanha(zj);
                float nh = tanha(nc)*sigt(zo);
                bool v = (ci < 2) ? v0 : v1;
                if (v){ c_reg[ci] = nc; h_reg[ci] = nh; }
            }
        }

        // write new h pairs to the global exchange buffer (L2)
        d_hbuf[dir][nxt][b0 + rb0][wslot] = packh2(h_reg[0], h_reg[1]);
        d_hbuf[dir][nxt][b0 + rb1][wslot] = packh2(h_reg[2], h_reg[3]);

        // prefetch next step's xz (flies under barrier + next stage + MMA)
        if (t + 1 < SEQT){
            int tn = dir ? (SEQT - 2 - t) : (t + 1);
            int id0 = __ldg(&ids[row0 + tn]);
            int id1 = __ldg(&ids[row1 + tn]);
            const float* p0 = &d_proj[id0][dir*GATES];
            const float* p1 = &d_proj[id1][dir*GATES];
            xzn0 = *(const float4*)&p0[(h0 + hc0    )*4];
            xzn1 = *(const float4*)&p0[(h0 + hc0 + 1)*4];
            xzn2 = *(const float4*)&p1[(h0 + hc0    )*4];
            xzn3 = *(const float4*)&p1[(h0 + hc0 + 1)*4];
        }

        asm volatile("barrier.cluster.arrive.aligned;" ::: "memory");
    }
    asm volatile("barrier.cluster.wait.aligned;" ::: "memory");

    // write fp32 final hidden state
    d_hfinal[dir][b0 + rb0][h0 + hc0    ] = h_reg[0];
    d_hfinal[dir][b0 + rb0][h0 + hc0 + 1] = h_reg[1];
    d_hfinal[dir][b0 + rb1][h0 + hc0    ] = h_reg[2];
    d_hfinal[dir][b0 + rb1][h0 + hc0 + 1] = h_reg[3];
}

// ---------------------------------------------------------------------------
// Kernel 4: final projection scores = [h_fw | h_bw] @ W_out + b_out
// ---------------------------------------------------------------------------
__global__ void k_out(const float* __restrict__ Wout, const float* __restrict__ bout,
                      float* __restrict__ out){
    int b = blockIdx.x;
    int tid = threadIdx.x;
    float s0 = 0.0f, s1 = 0.0f;
    for (int k = tid; k < 512; k += 256){
        float v = (k < 256) ? d_hfinal[0][b][k] : d_hfinal[1][b][k - 256];
        s0 += v*Wout[2*k];
        s1 += v*Wout[2*k + 1];
    }
    #pragma unroll
    for (int o = 16; o; o >>= 1){
        s0 += __shfl_down_sync(0xffffffffu, s0, o);
        s1 += __shfl_down_sync(0xffffffffu, s1, o);
    }
    __shared__ float r0[8], r1[8];
    int w = tid >> 5;
    if ((tid & 31) == 0){ r0[w] = s0; r1[w] = s1; }
    __syncthreads();
    if (tid == 0){
        float t0 = bout[0], t1 = bout[1];
        #pragma unroll
        for (int i = 0; i < 8; i++){ t0 += r0[i]; t1 += r1[i]; }
        out[2*b]     = t0;
        out[2*b + 1] = t1;
    }
}

// ---------------------------------------------------------------------------
extern "C" void kernel_launch(void* const* d_in, const int* in_sizes, int n_in,
                              void* d_out, int out_size){
    const int*   ids  = (const int*)  d_in[0];
    const float* emb  = (const float*)d_in[1];
    const float* Wfw  = (const float*)d_in[2];
    const float* bfw  = (const float*)d_in[3];
    const float* Wbw  = (const float*)d_in[4];
    const float* bbw  = (const float*)d_in[5];
    const float* Wout = (const float*)d_in[6];
    const float* bout = (const float*)d_in[7];
    float* out = (float*)d_out;

    cudaFuncSetAttribute(k_rnn, cudaFuncAttributeMaxDynamicSharedMemorySize, SMEM_RNN);

    k_init<<<BATCH, 128>>>(ids);
    k_cvt_emb<<<(VOCAB*76 + 255)/256, 256>>>(emb);
    k_cvt_w<<<(2*GATES*76 + 255)/256, 256>>>(Wfw, Wbw);
    dim3 g2(16, (VOCAB + 127)/128);
    k_vgemm<<<g2, 256>>>(bfw, bbw);
    k_rnn<<<NBLK, 256, SMEM_RNN>>>(Wfw, Wbw, ids);
    k_out<<<BATCH, 256>>>(Wout, bout, out);
}